// round 4
// baseline (speedup 1.0000x reference)
#include <cuda_runtime.h>
#include <cuda_bf16.h>
#include <cstdint>

// ---------------- problem constants ----------------
#define T_TOK 1024
#define HDIM  1024
#define IDIM  1024
#define NEXP  16
#define TOPK  4
#define LIMIT 7.0f
#define ALPHA 1.702f
#define EPS   1e-5f

// ---------------- scratch ----------------
__device__ __nv_bfloat16 g_xn[(size_t)T_TOK * HDIM];
__device__ __nv_bfloat16 g_s[(size_t)NEXP * T_TOK * IDIM];
__device__ float         g_y[(size_t)NEXP * T_TOK * HDIM];
__device__ int           g_tok[NEXP * T_TOK];
__device__ float         g_gate[NEXP * T_TOK];
__device__ int           g_slot_of[T_TOK * TOPK];
__device__ int           g_cnt[NEXP];

// ---------------- helpers ----------------
__device__ __forceinline__ uint32_t smem_u32(const void* p) {
    return (uint32_t)__cvta_generic_to_shared(p);
}
__device__ __forceinline__ void cp16(uint32_t s, const void* g) {
    asm volatile("cp.async.cg.shared.global [%0],[%1],16;\n" :: "r"(s), "l"(g));
}
__device__ __forceinline__ void cp_commit() { asm volatile("cp.async.commit_group;\n"); }
__device__ __forceinline__ void cp_wait0()  { asm volatile("cp.async.wait_group 0;\n"); }

__device__ __forceinline__ void ldsm_x4(uint32_t& r0, uint32_t& r1, uint32_t& r2, uint32_t& r3, uint32_t a) {
    asm volatile("ldmatrix.sync.aligned.m8n8.x4.shared.b16 {%0,%1,%2,%3},[%4];\n"
                 : "=r"(r0), "=r"(r1), "=r"(r2), "=r"(r3) : "r"(a));
}
__device__ __forceinline__ void ldsm_x4_t(uint32_t& r0, uint32_t& r1, uint32_t& r2, uint32_t& r3, uint32_t a) {
    asm volatile("ldmatrix.sync.aligned.m8n8.x4.trans.shared.b16 {%0,%1,%2,%3},[%4];\n"
                 : "=r"(r0), "=r"(r1), "=r"(r2), "=r"(r3) : "r"(a));
}
__device__ __forceinline__ void mma_bf16(float c[4],
                                         uint32_t a0, uint32_t a1, uint32_t a2, uint32_t a3,
                                         uint32_t b0, uint32_t b1) {
    asm volatile("mma.sync.aligned.m16n8k16.row.col.f32.bf16.bf16.f32 "
                 "{%0,%1,%2,%3},{%4,%5,%6,%7},{%8,%9},{%0,%1,%2,%3};\n"
                 : "+f"(c[0]), "+f"(c[1]), "+f"(c[2]), "+f"(c[3])
                 : "r"(a0), "r"(a1), "r"(a2), "r"(a3), "r"(b0), "r"(b1));
}
__device__ __forceinline__ float swiglu(float hg, float hl) {
    float a  = fminf(hg, LIMIT);
    float bb = fminf(fmaxf(hl, -LIMIT), LIMIT);
    return a * (1.0f / (1.0f + expf(-ALPHA * a))) * (bb + 1.0f);
}

// ---------------- kernel 0 ----------------
__global__ void zero_cnt_kernel() {
    if (threadIdx.x < NEXP) g_cnt[threadIdx.x] = 0;
}

// ---------------- kernel 1: RMSNorm + fp32 router + top-4 + scatter ----------------
__global__ void __launch_bounds__(256) rms_router_kernel(
    const float* __restrict__ x, const float* __restrict__ nscale,
    const float* __restrict__ wg, const float* __restrict__ bg) {
    int t   = blockIdx.x;
    int tid = threadIdx.x;
    __shared__ float xs[HDIM];
    __shared__ float red[256];
    __shared__ float l16[NEXP];

    float4 v = ((const float4*)(x + (size_t)t * HDIM))[tid];
    float ss = v.x * v.x + v.y * v.y + v.z * v.z + v.w * v.w;
    #pragma unroll
    for (int o = 16; o; o >>= 1) ss += __shfl_xor_sync(0xFFFFFFFFu, ss, o);
    if ((tid & 31) == 0) red[tid >> 5] = ss;
    __syncthreads();
    if (tid == 0) {
        float s = 0.f;
        #pragma unroll
        for (int i = 0; i < 8; i++) s += red[i];
        red[0] = rsqrtf(s * (1.0f / HDIM) + EPS);
    }
    __syncthreads();
    float r = red[0];
    float4 sc = ((const float4*)nscale)[tid];
    float4 xn4 = make_float4(v.x * r * sc.x, v.y * r * sc.y, v.z * r * sc.z, v.w * r * sc.w);
    xs[tid * 4 + 0] = xn4.x; xs[tid * 4 + 1] = xn4.y;
    xs[tid * 4 + 2] = xn4.z; xs[tid * 4 + 3] = xn4.w;
    __nv_bfloat162* dst = (__nv_bfloat162*)(g_xn + (size_t)t * HDIM);
    dst[tid * 2 + 0] = __floats2bfloat162_rn(xn4.x, xn4.y);
    dst[tid * 2 + 1] = __floats2bfloat162_rn(xn4.z, xn4.w);
    __syncthreads();

    int e  = tid & 15;
    int hl = tid >> 4;
    float acc = 0.f;
    #pragma unroll 8
    for (int j = 0; j < 64; j++) {
        int h = hl + j * 16;
        acc += xs[h] * wg[h * NEXP + e];
    }
    red[tid] = acc;
    __syncthreads();
    if (tid < 128) red[tid] += red[tid + 128];
    __syncthreads();
    if (tid < 64) red[tid] += red[tid + 64];
    __syncthreads();
    if (tid < 32) red[tid] += red[tid + 32];
    __syncthreads();
    if (tid < 16) l16[tid] = red[tid] + red[tid + 16] + bg[tid];
    __syncthreads();

    if (tid == 0) {
        float vals[TOPK];
        int   ids[TOPK];
        unsigned mask = 0;
        #pragma unroll
        for (int k = 0; k < TOPK; k++) {
            float best = -1e30f; int bi = 0;
            #pragma unroll
            for (int e2 = 0; e2 < NEXP; e2++) {
                if (!((mask >> e2) & 1u) && l16[e2] > best) { best = l16[e2]; bi = e2; }
            }
            mask |= 1u << bi; vals[k] = best; ids[k] = bi;
        }
        float m = vals[0], sum = 0.f, g[TOPK];
        #pragma unroll
        for (int k = 0; k < TOPK; k++) { g[k] = expf(vals[k] - m); sum += g[k]; }
        float inv = 1.0f / sum;
        #pragma unroll
        for (int k = 0; k < TOPK; k++) {
            int ee  = ids[k];
            int pos = atomicAdd(&g_cnt[ee], 1);
            int slot = ee * T_TOK + pos;
            g_tok[slot]  = t;
            g_gate[slot] = g[k] * inv;
            g_slot_of[t * TOPK + k] = slot;
        }
    }
}

// ---------------- grouped GEMM config ----------------
#define BM 256
#define BN 128
#define BK 32
#define NTHR 512
#define AS_STR (BK + 8)    // 40 bf16 = 80B rows
#define BS_STR (BN + 8)    // 136 bf16 = 272B rows
#define NIT (HDIM / BK)    // 32

// smem layout (dynamic):
#define SM_AS   0                         // [2][BM*AS_STR] bf16 = 2*20480B
#define SM_BS   (2 * BM * AS_STR * 2)     // [2][BK*BS_STR] bf16 = 2*8704B
#define SM_TOKS (SM_BS + 2 * BK * BS_STR * 2)
#define SMEM_BYTES (SM_TOKS + BM * 4)

// warp tile: 32(m) x 64(n); 16 warps: (warp>>1)*32 m, (warp&1)*64 n
__device__ __forceinline__ void mma_tile(float c[2][8][4],
                                         const __nv_bfloat16* As, const __nv_bfloat16* Bs,
                                         int mw, int nw, int lane) {
    #pragma unroll
    for (int ks = 0; ks < 2; ks++) {
        int kk = ks * 16;
        uint32_t a[2][4], b[8][2];
        #pragma unroll
        for (int mt = 0; mt < 2; mt++) {
            int rowm = mw + mt * 16 + (lane & 15);
            int colk = kk + ((lane >> 4) << 3);
            ldsm_x4(a[mt][0], a[mt][1], a[mt][2], a[mt][3],
                    smem_u32(&As[rowm * AS_STR + colk]));
        }
        #pragma unroll
        for (int np = 0; np < 4; np++) {
            int krow = kk + (lane & 15);
            int ncol = nw + np * 16 + ((lane >> 4) << 3);
            ldsm_x4_t(b[np * 2][0], b[np * 2][1], b[np * 2 + 1][0], b[np * 2 + 1][1],
                      smem_u32(&Bs[krow * BS_STR + ncol]));
        }
        #pragma unroll
        for (int mt = 0; mt < 2; mt++)
            #pragma unroll
            for (int nt = 0; nt < 8; nt++)
                mma_bf16(c[mt][nt], a[mt][0], a[mt][1], a[mt][2], a[mt][3],
                         b[nt][0], b[nt][1]);
    }
}

// ---------------- fused FFN kernel (templated) ----------------
template<bool FFN1>
__global__ void __launch_bounds__(NTHR, 1) ffn_kernel(const float* __restrict__ w,
                                                      const float* __restrict__ bias) {
    int e = blockIdx.z;
    int cnt = g_cnt[e];
    int row0 = blockIdx.y * BM;
    if (row0 >= cnt) return;
    int n0 = blockIdx.x * BN;

    extern __shared__ __align__(16) char smem[];
    __nv_bfloat16* As = (__nv_bfloat16*)(smem + SM_AS);
    __nv_bfloat16* Bs = (__nv_bfloat16*)(smem + SM_BS);
    int* toks = (int*)(smem + SM_TOKS);

    int tid = threadIdx.x;
    if (tid < BM) {
        int rr = min(row0 + tid, cnt - 1);
        toks[tid] = FFN1 ? g_tok[e * T_TOK + rr] : (e * T_TOK + rr);
    }
    __syncthreads();

    int warp = tid >> 5, lane = tid & 31;
    int mw = (warp >> 1) * 32;
    int nw = (warp & 1) * 64;
    float c[2][8][4];
    #pragma unroll
    for (int i = 0; i < 2; i++)
        #pragma unroll
        for (int j = 0; j < 8; j++)
            #pragma unroll
            for (int q = 0; q < 4; q++) c[i][j][q] = 0.f;

    const __nv_bfloat16* asrc = FFN1 ? g_xn : g_s;
    const int ldw = FFN1 ? (2 * IDIM) : HDIM;
    const float* wbase = w + (size_t)e * HDIM * ldw + n0;

    // A: 1024 16B-chunks, 2 per thread
    int ach0 = tid, ach1 = tid + NTHR;
    int ar0 = ach0 >> 2, ac0 = (ach0 & 3) * 8;
    int ar1 = ach1 >> 2, ac1 = (ach1 & 3) * 8;
    // For FFN1 tokens index g_xn rows; for FFN2 toks already absolute row in g_s
    size_t arow0 = FFN1 ? ((size_t)0) : 0; (void)arow0;
    // B: thread -> k-row tid>>4 (0..31), 8 floats at (tid&15)*8
    int bkr = tid >> 4, bc8 = (tid & 15) * 8;

    // prologue
    cp16(smem_u32(&As[0 * BM * AS_STR + ar0 * AS_STR + ac0]),
         asrc + ((size_t)toks[ar0] << 10) + ac0);
    cp16(smem_u32(&As[0 * BM * AS_STR + ar1 * AS_STR + ac1]),
         asrc + ((size_t)toks[ar1] << 10) + ac1);
    cp_commit();
    float4 bp0 = *(const float4*)(wbase + (size_t)bkr * ldw + bc8);
    float4 bp1 = *(const float4*)(wbase + (size_t)bkr * ldw + bc8 + 4);
    {
        __nv_bfloat162 p0 = __floats2bfloat162_rn(bp0.x, bp0.y);
        __nv_bfloat162 p1 = __floats2bfloat162_rn(bp0.z, bp0.w);
        __nv_bfloat162 p2 = __floats2bfloat162_rn(bp1.x, bp1.y);
        __nv_bfloat162 p3 = __floats2bfloat162_rn(bp1.z, bp1.w);
        *(uint4*)&Bs[bkr * BS_STR + bc8] =
            make_uint4(*(uint32_t*)&p0, *(uint32_t*)&p1, *(uint32_t*)&p2, *(uint32_t*)&p3);
    }
    cp_wait0();
    __syncthreads();

    for (int it = 0; it < NIT; it++) {
        int cur = it & 1, nxt = cur ^ 1;
        int k1 = (it + 1) * BK;
        if (it + 1 < NIT) {
            cp16(smem_u32(&As[nxt * BM * AS_STR + ar0 * AS_STR + ac0]),
                 asrc + ((size_t)toks[ar0] << 10) + k1 + ac0);
            cp16(smem_u32(&As[nxt * BM * AS_STR + ar1 * AS_STR + ac1]),
                 asrc + ((size_t)toks[ar1] << 10) + k1 + ac1);
            cp_commit();
            bp0 = *(const float4*)(wbase + (size_t)(k1 + bkr) * ldw + bc8);
            bp1 = *(const float4*)(wbase + (size_t)(k1 + bkr) * ldw + bc8 + 4);
        }
        mma_tile(c, &As[cur * BM * AS_STR], &Bs[cur * BK * BS_STR], mw, nw, lane);
        if (it + 1 < NIT) {
            __nv_bfloat162 p0 = __floats2bfloat162_rn(bp0.x, bp0.y);
            __nv_bfloat162 p1 = __floats2bfloat162_rn(bp0.z, bp0.w);
            __nv_bfloat162 p2 = __floats2bfloat162_rn(bp1.x, bp1.y);
            __nv_bfloat162 p3 = __floats2bfloat162_rn(bp1.z, bp1.w);
            *(uint4*)&Bs[nxt * BK * BS_STR + bkr * BS_STR + bc8] =
                make_uint4(*(uint32_t*)&p0, *(uint32_t*)&p1, *(uint32_t*)&p2, *(uint32_t*)&p3);
        }
        cp_wait0();
        __syncthreads();
    }

    // ---------------- epilogue ----------------
    int lr = lane >> 2, lc2 = lane & 3;
    if (FFN1) {
        const float* be = bias + e * (2 * IDIM);
        #pragma unroll
        for (int mt = 0; mt < 2; mt++) {
            #pragma unroll
            for (int nt = 0; nt < 8; nt++) {
                int ncol = n0 + nw + nt * 8 + lc2 * 2;
                float bb0 = be[ncol], bb1 = be[ncol + 1];
                int scol = ((n0 + nw) >> 1) + nt * 4 + lc2;
                int rl = mw + mt * 16 + lr;
                if (row0 + rl < cnt) {
                    float s = swiglu(c[mt][nt][0] + bb0, c[mt][nt][1] + bb1);
                    g_s[(size_t)(e * T_TOK + row0 + rl) * IDIM + scol] = __float2bfloat16(s);
                }
                if (row0 + rl + 8 < cnt) {
                    float s = swiglu(c[mt][nt][2] + bb0, c[mt][nt][3] + bb1);
                    g_s[(size_t)(e * T_TOK + row0 + rl + 8) * IDIM + scol] = __float2bfloat16(s);
                }
            }
        }
    } else {
        const float* be = bias + e * HDIM;
        #pragma unroll
        for (int mt = 0; mt < 2; mt++) {
            int rl = mw + mt * 16 + lr;
            #pragma unroll
            for (int nt = 0; nt < 8; nt++) {
                int ncol = n0 + nw + nt * 8 + lc2 * 2;
                float bb0 = be[ncol], bb1 = be[ncol + 1];
                if (row0 + rl < cnt) {
                    float gate = g_gate[e * T_TOK + row0 + rl];
                    float2 yv = make_float2((c[mt][nt][0] + bb0) * gate,
                                            (c[mt][nt][1] + bb1) * gate);
                    *(float2*)&g_y[(size_t)(e * T_TOK + row0 + rl) * HDIM + ncol] = yv;
                }
                if (row0 + rl + 8 < cnt) {
                    float gate = g_gate[e * T_TOK + row0 + rl + 8];
                    float2 yv = make_float2((c[mt][nt][2] + bb0) * gate,
                                            (c[mt][nt][3] + bb1) * gate);
                    *(float2*)&g_y[(size_t)(e * T_TOK + row0 + rl + 8) * HDIM + ncol] = yv;
                }
            }
        }
    }
}

// ---------------- kernel 4: combine ----------------
__global__ void __launch_bounds__(256) combine_kernel(const float* __restrict__ x,
                                                      float* __restrict__ out) {
    int t = blockIdx.x;
    int tid = threadIdx.x;
    int s0 = g_slot_of[t * TOPK + 0];
    int s1 = g_slot_of[t * TOPK + 1];
    int s2 = g_slot_of[t * TOPK + 2];
    int s3 = g_slot_of[t * TOPK + 3];
    size_t off = (size_t)tid * 4;
    float4 a = *(const float4*)(x + (size_t)t * HDIM + off);
    float4 y0 = *(const float4*)(g_y + (size_t)s0 * HDIM + off);
    float4 y1 = *(const float4*)(g_y + (size_t)s1 * HDIM + off);
    float4 y2 = *(const float4*)(g_y + (size_t)s2 * HDIM + off);
    float4 y3 = *(const float4*)(g_y + (size_t)s3 * HDIM + off);
    a.x += y0.x + y1.x + y2.x + y3.x;
    a.y += y0.y + y1.y + y2.y + y3.y;
    a.z += y0.z + y1.z + y2.z + y3.z;
    a.w += y0.w + y1.w + y2.w + y3.w;
    *(float4*)(out + (size_t)t * HDIM + off) = a;
}

// ---------------- launch ----------------
extern "C" void kernel_launch(void* const* d_in, const int* in_sizes, int n_in,
                              void* d_out, int out_size) {
    const float* x      = (const float*)d_in[0];
    const float* nscale = (const float*)d_in[1];
    const float* wg     = (const float*)d_in[2];
    const float* bg     = (const float*)d_in[3];
    const float* w1     = (const float*)d_in[4];
    const float* b1     = (const float*)d_in[5];
    const float* w2     = (const float*)d_in[6];
    const float* b2     = (const float*)d_in[7];
    float* out = (float*)d_out;

    static bool attr_set = false;
    // (setting an attribute is idempotent & host-side; do it every call to stay stateless)
    cudaFuncSetAttribute(ffn_kernel<true>,
                         cudaFuncAttributeMaxDynamicSharedMemorySize, SMEM_BYTES);
    cudaFuncSetAttribute(ffn_kernel<false>,
                         cudaFuncAttributeMaxDynamicSharedMemorySize, SMEM_BYTES);
    (void)attr_set;

    zero_cnt_kernel<<<1, 32>>>();
    rms_router_kernel<<<T_TOK, 256>>>(x, nscale, wg, bg);
    ffn_kernel<true><<<dim3((2 * IDIM) / BN, T_TOK / BM, NEXP), NTHR, SMEM_BYTES>>>(w1, b1);
    ffn_kernel<false><<<dim3(HDIM / BN, T_TOK / BM, NEXP), NTHR, SMEM_BYTES>>>(w2, b2);
    combine_kernel<<<T_TOK, 256>>>(x, out);
}

// round 6
// speedup vs baseline: 1.4111x; 1.4111x over previous
#include <cuda_runtime.h>
#include <cuda_bf16.h>
#include <cstdint>

// ---------------- problem constants ----------------
#define T_TOK 1024
#define HDIM  1024
#define IDIM  1024
#define NEXP  16
#define TOPK  4
#define LIMIT 7.0f
#define ALPHA 1.702f
#define EPS   1e-5f

// ---------------- scratch ----------------
__device__ __nv_bfloat16 g_xn[(size_t)T_TOK * HDIM];
__device__ __nv_bfloat16 g_s[(size_t)NEXP * T_TOK * IDIM];
__device__ float         g_y[(size_t)NEXP * T_TOK * HDIM];
__device__ int           g_tok[NEXP * T_TOK];
__device__ float         g_gate[NEXP * T_TOK];
__device__ int           g_slot_of[T_TOK * TOPK];
__device__ int           g_cnt[NEXP];

// ---------------- helpers ----------------
__device__ __forceinline__ uint32_t smem_u32(const void* p) {
    return (uint32_t)__cvta_generic_to_shared(p);
}
__device__ __forceinline__ void cp16(void* s, const void* g) {
    asm volatile("cp.async.cg.shared.global [%0],[%1],16;\n" :: "r"(smem_u32(s)), "l"(g));
}
__device__ __forceinline__ void cp_commit() { asm volatile("cp.async.commit_group;\n"); }
__device__ __forceinline__ void cp_wait1()  { asm volatile("cp.async.wait_group 1;\n"); }
__device__ __forceinline__ void cp_wait0()  { asm volatile("cp.async.wait_group 0;\n"); }

__device__ __forceinline__ void ldsm_x4(uint32_t& r0, uint32_t& r1, uint32_t& r2, uint32_t& r3, uint32_t a) {
    asm volatile("ldmatrix.sync.aligned.m8n8.x4.shared.b16 {%0,%1,%2,%3},[%4];\n"
                 : "=r"(r0), "=r"(r1), "=r"(r2), "=r"(r3) : "r"(a));
}
__device__ __forceinline__ void ldsm_x4_t(uint32_t& r0, uint32_t& r1, uint32_t& r2, uint32_t& r3, uint32_t a) {
    asm volatile("ldmatrix.sync.aligned.m8n8.x4.trans.shared.b16 {%0,%1,%2,%3},[%4];\n"
                 : "=r"(r0), "=r"(r1), "=r"(r2), "=r"(r3) : "r"(a));
}
__device__ __forceinline__ void mma_bf16(float c[4],
                                         uint32_t a0, uint32_t a1, uint32_t a2, uint32_t a3,
                                         uint32_t b0, uint32_t b1) {
    asm volatile("mma.sync.aligned.m16n8k16.row.col.f32.bf16.bf16.f32 "
                 "{%0,%1,%2,%3},{%4,%5,%6,%7},{%8,%9},{%0,%1,%2,%3};\n"
                 : "+f"(c[0]), "+f"(c[1]), "+f"(c[2]), "+f"(c[3])
                 : "r"(a0), "r"(a1), "r"(a2), "r"(a3), "r"(b0), "r"(b1));
}
__device__ __forceinline__ float swiglu(float hg, float hl) {
    float a  = fminf(hg, LIMIT);
    float bb = fminf(fmaxf(hl, -LIMIT), LIMIT);
    return a * (1.0f / (1.0f + expf(-ALPHA * a))) * (bb + 1.0f);
}

// ---------------- kernel 0 ----------------
__global__ void zero_cnt_kernel() {
    if (threadIdx.x < NEXP) g_cnt[threadIdx.x] = 0;
}

// ---------------- kernel 1: RMSNorm + fp32 router + top-4 + scatter ----------------
__global__ void __launch_bounds__(256) rms_router_kernel(
    const float* __restrict__ x, const float* __restrict__ nscale,
    const float* __restrict__ wg, const float* __restrict__ bg) {
    int t   = blockIdx.x;
    int tid = threadIdx.x;
    __shared__ float xs[HDIM];
    __shared__ float red[256];
    __shared__ float l16[NEXP];

    float4 v = ((const float4*)(x + (size_t)t * HDIM))[tid];
    float ss = v.x * v.x + v.y * v.y + v.z * v.z + v.w * v.w;
    #pragma unroll
    for (int o = 16; o; o >>= 1) ss += __shfl_xor_sync(0xFFFFFFFFu, ss, o);
    if ((tid & 31) == 0) red[tid >> 5] = ss;
    __syncthreads();
    if (tid == 0) {
        float s = 0.f;
        #pragma unroll
        for (int i = 0; i < 8; i++) s += red[i];
        red[0] = rsqrtf(s * (1.0f / HDIM) + EPS);
    }
    __syncthreads();
    float r = red[0];
    float4 sc = ((const float4*)nscale)[tid];
    float4 xn4 = make_float4(v.x * r * sc.x, v.y * r * sc.y, v.z * r * sc.z, v.w * r * sc.w);
    xs[tid * 4 + 0] = xn4.x; xs[tid * 4 + 1] = xn4.y;
    xs[tid * 4 + 2] = xn4.z; xs[tid * 4 + 3] = xn4.w;
    __nv_bfloat162* dst = (__nv_bfloat162*)(g_xn + (size_t)t * HDIM);
    dst[tid * 2 + 0] = __floats2bfloat162_rn(xn4.x, xn4.y);
    dst[tid * 2 + 1] = __floats2bfloat162_rn(xn4.z, xn4.w);
    __syncthreads();

    int e  = tid & 15;
    int hl = tid >> 4;
    float acc = 0.f;
    #pragma unroll 8
    for (int j = 0; j < 64; j++) {
        int h = hl + j * 16;
        acc += xs[h] * wg[h * NEXP + e];
    }
    red[tid] = acc;
    __syncthreads();
    if (tid < 128) red[tid] += red[tid + 128];
    __syncthreads();
    if (tid < 64) red[tid] += red[tid + 64];
    __syncthreads();
    if (tid < 32) red[tid] += red[tid + 32];
    __syncthreads();
    if (tid < 16) l16[tid] = red[tid] + red[tid + 16] + bg[tid];
    __syncthreads();

    if (tid == 0) {
        float vals[TOPK];
        int   ids[TOPK];
        unsigned mask = 0;
        #pragma unroll
        for (int k = 0; k < TOPK; k++) {
            float best = -1e30f; int bi = 0;
            #pragma unroll
            for (int e2 = 0; e2 < NEXP; e2++) {
                if (!((mask >> e2) & 1u) && l16[e2] > best) { best = l16[e2]; bi = e2; }
            }
            mask |= 1u << bi; vals[k] = best; ids[k] = bi;
        }
        float m = vals[0], sum = 0.f, g[TOPK];
        #pragma unroll
        for (int k = 0; k < TOPK; k++) { g[k] = expf(vals[k] - m); sum += g[k]; }
        float inv = 1.0f / sum;
        #pragma unroll
        for (int k = 0; k < TOPK; k++) {
            int ee  = ids[k];
            int pos = atomicAdd(&g_cnt[ee], 1);
            int slot = ee * T_TOK + pos;
            g_tok[slot]  = t;
            g_gate[slot] = g[k] * inv;
            g_slot_of[t * TOPK + k] = slot;
        }
    }
}

// ---------------- grouped GEMM config ----------------
#define BM 128
#define BN 128
#define BK 32
#define AS_STR (BK + 8)    // 40 bf16 = 80B rows
#define BS_STR (BN + 8)    // 136 bf16 = 272B rows
#define AS_SZ  (BM * AS_STR)
#define BS_SZ  (BK * BS_STR)
#define NIT (HDIM / BK)    // 32

struct BPrefetch { float4 f[4]; };

__device__ __forceinline__ void loadB_regs(BPrefetch& p, const float* wrow, int c16) {
    #pragma unroll
    for (int j = 0; j < 4; j++) p.f[j] = *(const float4*)(wrow + c16 + j * 4);
}
__device__ __forceinline__ void storeB_smem(__nv_bfloat16* Bs, const BPrefetch& p, int kr, int c16) {
    uint32_t u[8];
    #pragma unroll
    for (int j = 0; j < 4; j++) {
        __nv_bfloat162 p0 = __floats2bfloat162_rn(p.f[j].x, p.f[j].y);
        __nv_bfloat162 p1 = __floats2bfloat162_rn(p.f[j].z, p.f[j].w);
        u[j * 2 + 0] = *(uint32_t*)&p0;
        u[j * 2 + 1] = *(uint32_t*)&p1;
    }
    uint4* d = (uint4*)&Bs[kr * BS_STR + c16];
    d[0] = make_uint4(u[0], u[1], u[2], u[3]);
    d[1] = make_uint4(u[4], u[5], u[6], u[7]);
}

// warp tile 32(m) x 64(n); 8 warps = 4m x 2n
__device__ __forceinline__ void mma_tile(float c[2][8][4],
                                         const __nv_bfloat16* As, const __nv_bfloat16* Bs,
                                         int mw, int nw, int lane) {
    #pragma unroll
    for (int ks = 0; ks < 2; ks++) {
        int kk = ks * 16;
        uint32_t a[2][4], b[8][2];
        #pragma unroll
        for (int mt = 0; mt < 2; mt++) {
            int rowm = mw + mt * 16 + (lane & 15);
            int colk = kk + ((lane >> 4) << 3);
            ldsm_x4(a[mt][0], a[mt][1], a[mt][2], a[mt][3],
                    smem_u32(&As[rowm * AS_STR + colk]));
        }
        #pragma unroll
        for (int np = 0; np < 4; np++) {
            int krow = kk + (lane & 15);
            int ncol = nw + np * 16 + ((lane >> 4) << 3);
            ldsm_x4_t(b[np * 2][0], b[np * 2][1], b[np * 2 + 1][0], b[np * 2 + 1][1],
                      smem_u32(&Bs[krow * BS_STR + ncol]));
        }
        #pragma unroll
        for (int mt = 0; mt < 2; mt++)
            #pragma unroll
            for (int nt = 0; nt < 8; nt++)
                mma_bf16(c[mt][nt], a[mt][0], a[mt][1], a[mt][2], a[mt][3],
                         b[nt][0], b[nt][1]);
    }
}

// ---------------- fused FFN kernel (templated) ----------------
template<bool FFN1>
__global__ void __launch_bounds__(256, 2) ffn_kernel(const float* __restrict__ w,
                                                     const float* __restrict__ bias) {
    int e = blockIdx.z;
    int cnt = g_cnt[e];
    int row0 = blockIdx.y * BM;
    if (row0 >= cnt) return;
    int n0 = blockIdx.x * BN;

    __shared__ __align__(16) __nv_bfloat16 As[3][AS_SZ];   // 3-stage A ring
    __shared__ __align__(16) __nv_bfloat16 Bs[2][BS_SZ];   // 2-stage B
    __shared__ int toks[BM];

    int tid = threadIdx.x;
    if (tid < BM) {
        int rr = min(row0 + tid, cnt - 1);
        toks[tid] = FFN1 ? g_tok[e * T_TOK + rr] : (e * T_TOK + rr);
    }
    __syncthreads();

    int warp = tid >> 5, lane = tid & 31;
    int mw = (warp >> 1) * 32;
    int nw = (warp & 1) * 64;
    float c[2][8][4];
    #pragma unroll
    for (int i = 0; i < 2; i++)
        #pragma unroll
        for (int j = 0; j < 8; j++)
            #pragma unroll
            for (int q = 0; q < 4; q++) c[i][j][q] = 0.f;

    const __nv_bfloat16* asrc = FFN1 ? g_xn : g_s;
    const int ldw = FFN1 ? (2 * IDIM) : HDIM;
    const float* wbase = w + (size_t)e * HDIM * ldw + n0;

    // A: 512 chunks of 16B, 2 per thread
    int ar0 = tid >> 2,         ac0 = (tid & 3) * 8;
    int ar1 = (tid + 256) >> 2, ac1 = ((tid + 256) & 3) * 8;
    const __nv_bfloat16* arow0 = asrc + ((size_t)toks[ar0] << 10) + ac0;
    const __nv_bfloat16* arow1 = asrc + ((size_t)toks[ar1] << 10) + ac1;
    // B: 1 k-row, 16 floats per thread
    int bkr = tid >> 3, bc16 = (tid & 7) * 16;

    // prologue: A(0), A(1) in flight; B(0) built
    cp16(&As[0][ar0 * AS_STR + ac0], arow0);
    cp16(&As[0][ar1 * AS_STR + ac1], arow1);
    cp_commit();
    cp16(&As[1][ar0 * AS_STR + ac0], arow0 + BK);
    cp16(&As[1][ar1 * AS_STR + ac1], arow1 + BK);
    cp_commit();
    BPrefetch bp;
    loadB_regs(bp, wbase + (size_t)bkr * ldw, bc16);
    storeB_smem(Bs[0], bp, bkr, bc16);
    cp_wait1();          // A(0) done, A(1) still flying
    __syncthreads();

    for (int it = 0; it < NIT; it++) {
        int cs = it % 3;      // A slot for this iter
        int cb = it & 1;      // B slot for this iter
        if (it + 2 < NIT) {   // issue A(it+2)
            int ka = (it + 2) * BK;
            int ns = (it + 2) % 3;
            cp16(&As[ns][ar0 * AS_STR + ac0], arow0 + ka);
            cp16(&As[ns][ar1 * AS_STR + ac1], arow1 + ka);
            cp_commit();
        }
        if (it + 1 < NIT) {
            int k1 = (it + 1) * BK;
            loadB_regs(bp, wbase + (size_t)(k1 + bkr) * ldw, bc16);
        }
        mma_tile(c, As[cs], Bs[cb], mw, nw, lane);
        if (it + 1 < NIT) storeB_smem(Bs[cb ^ 1], bp, bkr, bc16);
        if (it + 3 < NIT) cp_wait1(); else cp_wait0();   // A(it+1) ready
        __syncthreads();
    }

    // ---------------- epilogue ----------------
    int lr = lane >> 2, lc2 = lane & 3;
    if (FFN1) {
        const float* be = bias + e * (2 * IDIM);
        #pragma unroll
        for (int mt = 0; mt < 2; mt++) {
            #pragma unroll
            for (int nt = 0; nt < 8; nt++) {
                int ncol = n0 + nw + nt * 8 + lc2 * 2;
                float bb0 = be[ncol], bb1 = be[ncol + 1];
                int scol = ((n0 + nw) >> 1) + nt * 4 + lc2;
                int rl = mw + mt * 16 + lr;
                if (row0 + rl < cnt) {
                    float s = swiglu(c[mt][nt][0] + bb0, c[mt][nt][1] + bb1);
                    g_s[(size_t)(e * T_TOK + row0 + rl) * IDIM + scol] = __float2bfloat16(s);
                }
                if (row0 + rl + 8 < cnt) {
                    float s = swiglu(c[mt][nt][2] + bb0, c[mt][nt][3] + bb1);
                    g_s[(size_t)(e * T_TOK + row0 + rl + 8) * IDIM + scol] = __float2bfloat16(s);
                }
            }
        }
    } else {
        const float* be = bias + e * HDIM;
        #pragma unroll
        for (int mt = 0; mt < 2; mt++) {
            int rl = mw + mt * 16 + lr;
            #pragma unroll
            for (int nt = 0; nt < 8; nt++) {
                int ncol = n0 + nw + nt * 8 + lc2 * 2;
                float bb0 = be[ncol], bb1 = be[ncol + 1];
                if (row0 + rl < cnt) {
                    float gate = g_gate[e * T_TOK + row0 + rl];
                    float2 yv = make_float2((c[mt][nt][0] + bb0) * gate,
                                            (c[mt][nt][1] + bb1) * gate);
                    *(float2*)&g_y[(size_t)(e * T_TOK + row0 + rl) * HDIM + ncol] = yv;
                }
                if (row0 + rl + 8 < cnt) {
                    float gate = g_gate[e * T_TOK + row0 + rl + 8];
                    float2 yv = make_float2((c[mt][nt][2] + bb0) * gate,
                                            (c[mt][nt][3] + bb1) * gate);
                    *(float2*)&g_y[(size_t)(e * T_TOK + row0 + rl + 8) * HDIM + ncol] = yv;
                }
            }
        }
    }
}

// ---------------- kernel 4: combine ----------------
__global__ void __launch_bounds__(256) combine_kernel(const float* __restrict__ x,
                                                      float* __restrict__ out) {
    int t = blockIdx.x;
    int tid = threadIdx.x;
    int s0 = g_slot_of[t * TOPK + 0];
    int s1 = g_slot_of[t * TOPK + 1];
    int s2 = g_slot_of[t * TOPK + 2];
    int s3 = g_slot_of[t * TOPK + 3];
    size_t off = (size_t)tid * 4;
    float4 a = *(const float4*)(x + (size_t)t * HDIM + off);
    float4 y0 = *(const float4*)(g_y + (size_t)s0 * HDIM + off);
    float4 y1 = *(const float4*)(g_y + (size_t)s1 * HDIM + off);
    float4 y2 = *(const float4*)(g_y + (size_t)s2 * HDIM + off);
    float4 y3 = *(const float4*)(g_y + (size_t)s3 * HDIM + off);
    a.x += y0.x + y1.x + y2.x + y3.x;
    a.y += y0.y + y1.y + y2.y + y3.y;
    a.z += y0.z + y1.z + y2.z + y3.z;
    a.w += y0.w + y1.w + y2.w + y3.w;
    *(float4*)(out + (size_t)t * HDIM + off) = a;
}

// ---------------- launch ----------------
extern "C" void kernel_launch(void* const* d_in, const int* in_sizes, int n_in,
                              void* d_out, int out_size) {
    const float* x      = (const float*)d_in[0];
    const float* nscale = (const float*)d_in[1];
    const float* wg     = (const float*)d_in[2];
    const float* bg     = (const float*)d_in[3];
    const float* w1     = (const float*)d_in[4];
    const float* b1     = (const float*)d_in[5];
    const float* w2     = (const float*)d_in[6];
    const float* b2     = (const float*)d_in[7];
    float* out = (float*)d_out;

    zero_cnt_kernel<<<1, 32>>>();
    rms_router_kernel<<<T_TOK, 256>>>(x, nscale, wg, bg);
    ffn_kernel<true><<<dim3((2 * IDIM) / BN, T_TOK / BM, NEXP), 256>>>(w1, b1);
    ffn_kernel<false><<<dim3(HDIM / BN, T_TOK / BM, NEXP), 256>>>(w2, b2);
    combine_kernel<<<T_TOK, 256>>>(x, out);
}

// round 8
// speedup vs baseline: 1.5991x; 1.1333x over previous
#include <cuda_runtime.h>
#include <cuda_bf16.h>
#include <cstdint>

// ---------------- problem constants ----------------
#define T_TOK 1024
#define HDIM  1024
#define IDIM  1024
#define NEXP  16
#define TOPK  4
#define LIMIT 7.0f
#define ALPHA 1.702f
#define EPS   1e-5f

// ---------------- scratch ----------------
__device__ __nv_bfloat16 g_xn[(size_t)T_TOK * HDIM];
__device__ __nv_bfloat16 g_s[(size_t)NEXP * T_TOK * IDIM];
__device__ float         g_y[(size_t)NEXP * T_TOK * HDIM];
__device__ int           g_tok[NEXP * T_TOK];
__device__ float         g_gate[NEXP * T_TOK];
__device__ int           g_slot_of[T_TOK * TOPK];
__device__ int           g_cnt[NEXP];

// ---------------- helpers ----------------
__device__ __forceinline__ uint32_t smem_u32(const void* p) {
    return (uint32_t)__cvta_generic_to_shared(p);
}
__device__ __forceinline__ void cp16(void* s, const void* g) {
    asm volatile("cp.async.cg.shared.global [%0],[%1],16;\n" :: "r"(smem_u32(s)), "l"(g));
}
__device__ __forceinline__ void cp_commit() { asm volatile("cp.async.commit_group;\n"); }
__device__ __forceinline__ void cp_wait1()  { asm volatile("cp.async.wait_group 1;\n"); }
__device__ __forceinline__ void cp_wait0()  { asm volatile("cp.async.wait_group 0;\n"); }

__device__ __forceinline__ void ldsm_x4(uint32_t& r0, uint32_t& r1, uint32_t& r2, uint32_t& r3, uint32_t a) {
    asm volatile("ldmatrix.sync.aligned.m8n8.x4.shared.b16 {%0,%1,%2,%3},[%4];\n"
                 : "=r"(r0), "=r"(r1), "=r"(r2), "=r"(r3) : "r"(a));
}
__device__ __forceinline__ void ldsm_x4_t(uint32_t& r0, uint32_t& r1, uint32_t& r2, uint32_t& r3, uint32_t a) {
    asm volatile("ldmatrix.sync.aligned.m8n8.x4.trans.shared.b16 {%0,%1,%2,%3},[%4];\n"
                 : "=r"(r0), "=r"(r1), "=r"(r2), "=r"(r3) : "r"(a));
}
__device__ __forceinline__ void mma_bf16(float c[4],
                                         uint32_t a0, uint32_t a1, uint32_t a2, uint32_t a3,
                                         uint32_t b0, uint32_t b1) {
    asm volatile("mma.sync.aligned.m16n8k16.row.col.f32.bf16.bf16.f32 "
                 "{%0,%1,%2,%3},{%4,%5,%6,%7},{%8,%9},{%0,%1,%2,%3};\n"
                 : "+f"(c[0]), "+f"(c[1]), "+f"(c[2]), "+f"(c[3])
                 : "r"(a0), "r"(a1), "r"(a2), "r"(a3), "r"(b0), "r"(b1));
}
__device__ __forceinline__ float swiglu(float hg, float hl) {
    float a  = fminf(hg, LIMIT);
    float bb = fminf(fmaxf(hl, -LIMIT), LIMIT);
    return a * (1.0f / (1.0f + expf(-ALPHA * a))) * (bb + 1.0f);
}

// ---------------- kernel 0 ----------------
__global__ void zero_cnt_kernel() {
    if (threadIdx.x < NEXP) g_cnt[threadIdx.x] = 0;
}

// ---------------- kernel 1: RMSNorm + fp32 router + top-4 + scatter ----------------
__global__ void __launch_bounds__(256) rms_router_kernel(
    const float* __restrict__ x, const float* __restrict__ nscale,
    const float* __restrict__ wg, const float* __restrict__ bg) {
    int t   = blockIdx.x;
    int tid = threadIdx.x;
    __shared__ float xs[HDIM];
    __shared__ float red[256];
    __shared__ float l16[NEXP];

    float4 v = ((const float4*)(x + (size_t)t * HDIM))[tid];
    float ss = v.x * v.x + v.y * v.y + v.z * v.z + v.w * v.w;
    #pragma unroll
    for (int o = 16; o; o >>= 1) ss += __shfl_xor_sync(0xFFFFFFFFu, ss, o);
    if ((tid & 31) == 0) red[tid >> 5] = ss;
    __syncthreads();
    if (tid == 0) {
        float s = 0.f;
        #pragma unroll
        for (int i = 0; i < 8; i++) s += red[i];
        red[0] = rsqrtf(s * (1.0f / HDIM) + EPS);
    }
    __syncthreads();
    float r = red[0];
    float4 sc = ((const float4*)nscale)[tid];
    float4 xn4 = make_float4(v.x * r * sc.x, v.y * r * sc.y, v.z * r * sc.z, v.w * r * sc.w);
    xs[tid * 4 + 0] = xn4.x; xs[tid * 4 + 1] = xn4.y;
    xs[tid * 4 + 2] = xn4.z; xs[tid * 4 + 3] = xn4.w;
    __nv_bfloat162* dst = (__nv_bfloat162*)(g_xn + (size_t)t * HDIM);
    dst[tid * 2 + 0] = __floats2bfloat162_rn(xn4.x, xn4.y);
    dst[tid * 2 + 1] = __floats2bfloat162_rn(xn4.z, xn4.w);
    __syncthreads();

    int e  = tid & 15;
    int hl = tid >> 4;
    float acc = 0.f;
    #pragma unroll 8
    for (int j = 0; j < 64; j++) {
        int h = hl + j * 16;
        acc += xs[h] * wg[h * NEXP + e];
    }
    red[tid] = acc;
    __syncthreads();
    if (tid < 128) red[tid] += red[tid + 128];
    __syncthreads();
    if (tid < 64) red[tid] += red[tid + 64];
    __syncthreads();
    if (tid < 32) red[tid] += red[tid + 32];
    __syncthreads();
    if (tid < 16) l16[tid] = red[tid] + red[tid + 16] + bg[tid];
    __syncthreads();

    if (tid == 0) {
        float vals[TOPK];
        int   ids[TOPK];
        unsigned mask = 0;
        #pragma unroll
        for (int k = 0; k < TOPK; k++) {
            float best = -1e30f; int bi = 0;
            #pragma unroll
            for (int e2 = 0; e2 < NEXP; e2++) {
                if (!((mask >> e2) & 1u) && l16[e2] > best) { best = l16[e2]; bi = e2; }
            }
            mask |= 1u << bi; vals[k] = best; ids[k] = bi;
        }
        float m = vals[0], sum = 0.f, g[TOPK];
        #pragma unroll
        for (int k = 0; k < TOPK; k++) { g[k] = expf(vals[k] - m); sum += g[k]; }
        float inv = 1.0f / sum;
        #pragma unroll
        for (int k = 0; k < TOPK; k++) {
            int ee  = ids[k];
            int pos = atomicAdd(&g_cnt[ee], 1);
            int slot = ee * T_TOK + pos;
            g_tok[slot]  = t;
            g_gate[slot] = g[k] * inv;
            g_slot_of[t * TOPK + k] = slot;
        }
    }
}

// ---------------- grouped GEMM config ----------------
#define BM 128
#define BN 128
#define BK 32
#define AS_STR (BK + 8)    // 40 bf16 = 80B rows
#define BS_STR (BN + 8)    // 136 bf16 = 272B rows
#define AS_SZ  (BM * AS_STR)              // elems per A stage
#define BSB_SZ (BK * BS_STR)              // elems per bf16 B stage
#define BF_SZ  (BK * BN)                  // floats per fp32 B stage (4096)
#define NIT (HDIM / BK)    // 32

// dynamic smem layout (bytes)
#define OFF_AS   0
#define OFF_BF   (OFF_AS + 3 * AS_SZ * 2)          // 30720
#define OFF_BSB  (OFF_BF + 3 * BF_SZ * 4)          // 79872
#define OFF_TOKS (OFF_BSB + 2 * BSB_SZ * 2)        // 97280
#define SMEM_BYTES (OFF_TOKS + BM * 4)             // 97792

// warp tile 32(m) x 64(n); 8 warps = 4m x 2n
__device__ __forceinline__ void mma_tile(float c[2][8][4],
                                         const __nv_bfloat16* As, const __nv_bfloat16* Bs,
                                         int mw, int nw, int lane) {
    #pragma unroll
    for (int ks = 0; ks < 2; ks++) {
        int kk = ks * 16;
        uint32_t a[2][4], b[8][2];
        #pragma unroll
        for (int mt = 0; mt < 2; mt++) {
            int rowm = mw + mt * 16 + (lane & 15);
            int colk = kk + ((lane >> 4) << 3);
            ldsm_x4(a[mt][0], a[mt][1], a[mt][2], a[mt][3],
                    smem_u32(&As[rowm * AS_STR + colk]));
        }
        #pragma unroll
        for (int np = 0; np < 4; np++) {
            int krow = kk + (lane & 15);
            int ncol = nw + np * 16 + ((lane >> 4) << 3);
            ldsm_x4_t(b[np * 2][0], b[np * 2][1], b[np * 2 + 1][0], b[np * 2 + 1][1],
                      smem_u32(&Bs[krow * BS_STR + ncol]));
        }
        #pragma unroll
        for (int mt = 0; mt < 2; mt++)
            #pragma unroll
            for (int nt = 0; nt < 8; nt++)
                mma_bf16(c[mt][nt], a[mt][0], a[mt][1], a[mt][2], a[mt][3],
                         b[nt][0], b[nt][1]);
    }
}

// ---------------- fused FFN kernel (templated) ----------------
template<bool FFN1>
__global__ void __launch_bounds__(256, 2) ffn_kernel(const float* __restrict__ w,
                                                     const float* __restrict__ bias) {
    int e = blockIdx.z;
    int cnt = g_cnt[e];
    int row0 = blockIdx.y * BM;
    if (row0 >= cnt) return;
    int n0 = blockIdx.x * BN;

    extern __shared__ __align__(16) char smem[];
    __nv_bfloat16* As  = (__nv_bfloat16*)(smem + OFF_AS);
    float*         Bf  = (float*)(smem + OFF_BF);
    __nv_bfloat16* Bsb = (__nv_bfloat16*)(smem + OFF_BSB);
    int*          toks = (int*)(smem + OFF_TOKS);

    int tid = threadIdx.x;
    if (tid < BM) {
        int rr = min(row0 + tid, cnt - 1);
        toks[tid] = FFN1 ? g_tok[e * T_TOK + rr] : (e * T_TOK + rr);
    }
    __syncthreads();

    int warp = tid >> 5, lane = tid & 31;
    int mw = (warp >> 1) * 32;
    int nw = (warp & 1) * 64;
    float c[2][8][4];
    #pragma unroll
    for (int i = 0; i < 2; i++)
        #pragma unroll
        for (int j = 0; j < 8; j++)
            #pragma unroll
            for (int q = 0; q < 4; q++) c[i][j][q] = 0.f;

    const __nv_bfloat16* asrc = FFN1 ? g_xn : g_s;
    const int ldw = FFN1 ? (2 * IDIM) : HDIM;
    const float* wbase = w + (size_t)e * HDIM * ldw + n0;

    // A: 512 16B-chunks, 2 per thread
    int ar0 = tid >> 2,         ac0 = (tid & 3) * 8;
    int ar1 = (tid + 256) >> 2, ac1 = ((tid + 256) & 3) * 8;
    const __nv_bfloat16* arow0 = asrc + ((size_t)toks[ar0] << 10) + ac0;
    const __nv_bfloat16* arow1 = asrc + ((size_t)toks[ar1] << 10) + ac1;

    // B chunks: c = tid + 256*j (j=0..3); kr=c>>5 (k-row), c16=c&31 (16B col)
    // fp32 ring stage is laid out linearly: byte offset = c*16

    // --- producers ---
    auto issueA = [&](int it) {
        int slot = it % 3, ka = it * BK;
        cp16(&As[slot * AS_SZ + ar0 * AS_STR + ac0], arow0 + ka);
        cp16(&As[slot * AS_SZ + ar1 * AS_STR + ac1], arow1 + ka);
    };
    auto issueB = [&](int it) {
        int slot = it % 3, k0 = it * BK;
        float* dst = Bf + slot * BF_SZ;
        #pragma unroll
        for (int j = 0; j < 4; j++) {
            int cch = tid + 256 * j;
            int kr = cch >> 5, c16 = cch & 31;
            cp16(dst + cch * 4, wbase + (size_t)(k0 + kr) * ldw + c16 * 4);
        }
    };
    // convert stage (it) fp32 -> bf16 buffer (it&1); conflict-free LDS128/STS64
    auto cvtB = [&](int it) {
        int slot = it % 3;
        const float* src = Bf + slot * BF_SZ;
        __nv_bfloat16* dst = Bsb + (it & 1) * BSB_SZ;
        #pragma unroll
        for (int j = 0; j < 4; j++) {
            int cch = tid + 256 * j;
            int kr = cch >> 5, c16 = cch & 31;
            float4 v = *(const float4*)(src + cch * 4);
            __nv_bfloat162 p0 = __floats2bfloat162_rn(v.x, v.y);
            __nv_bfloat162 p1 = __floats2bfloat162_rn(v.z, v.w);
            uint2 u = make_uint2(*(uint32_t*)&p0, *(uint32_t*)&p1);
            *(uint2*)&dst[kr * BS_STR + c16 * 4] = u;
        }
    };

    // prologue: groups G(-2)=tile0, G(-1)=tile1 in flight
    issueA(0); issueB(0); cp_commit();
    issueA(1); issueB(1); cp_commit();
    cp_wait1();              // tile0 landed (self-visible)
    cvtB(0);                 // own chunks only -> no sync needed before
    __syncthreads();         // publish Bsb[0] (+As tile0 via later wait ordering)

    for (int it = 0; it < NIT; it++) {
        if (it + 2 < NIT) { issueA(it + 2); issueB(it + 2); }
        cp_commit();          // always commit (possibly empty) -> uniform accounting
        cp_wait1();           // tile (it+1) data landed (self-visible)
        if (it + 1 < NIT) cvtB(it + 1);
        mma_tile(c, &As[(it % 3) * AS_SZ], &Bsb[(it & 1) * BSB_SZ], mw, nw, lane);
        __syncthreads();      // publish Bsb[(it+1)&1] and As tile (it+1)
    }

    // ---------------- epilogue ----------------
    int lr = lane >> 2, lc2 = lane & 3;
    if (FFN1) {
        const float* be = bias + e * (2 * IDIM);
        #pragma unroll
        for (int mt = 0; mt < 2; mt++) {
            #pragma unroll
            for (int nt = 0; nt < 8; nt++) {
                int ncol = n0 + nw + nt * 8 + lc2 * 2;
                float bb0 = be[ncol], bb1 = be[ncol + 1];
                int scol = ((n0 + nw) >> 1) + nt * 4 + lc2;
                int rl = mw + mt * 16 + lr;
                if (row0 + rl < cnt) {
                    float s = swiglu(c[mt][nt][0] + bb0, c[mt][nt][1] + bb1);
                    g_s[(size_t)(e * T_TOK + row0 + rl) * IDIM + scol] = __float2bfloat16(s);
                }
                if (row0 + rl + 8 < cnt) {
                    float s = swiglu(c[mt][nt][2] + bb0, c[mt][nt][3] + bb1);
                    g_s[(size_t)(e * T_TOK + row0 + rl + 8) * IDIM + scol] = __float2bfloat16(s);
                }
            }
        }
    } else {
        const float* be = bias + e * HDIM;
        #pragma unroll
        for (int mt = 0; mt < 2; mt++) {
            int rl = mw + mt * 16 + lr;
            #pragma unroll
            for (int nt = 0; nt < 8; nt++) {
                int ncol = n0 + nw + nt * 8 + lc2 * 2;
                float bb0 = be[ncol], bb1 = be[ncol + 1];
                if (row0 + rl < cnt) {
                    float gate = g_gate[e * T_TOK + row0 + rl];
                    float2 yv = make_float2((c[mt][nt][0] + bb0) * gate,
                                            (c[mt][nt][1] + bb1) * gate);
                    *(float2*)&g_y[(size_t)(e * T_TOK + row0 + rl) * HDIM + ncol] = yv;
                }
                if (row0 + rl + 8 < cnt) {
                    float gate = g_gate[e * T_TOK + row0 + rl + 8];
                    float2 yv = make_float2((c[mt][nt][2] + bb0) * gate,
                                            (c[mt][nt][3] + bb1) * gate);
                    *(float2*)&g_y[(size_t)(e * T_TOK + row0 + rl + 8) * HDIM + ncol] = yv;
                }
            }
        }
    }
}

// ---------------- kernel 4: combine ----------------
__global__ void __launch_bounds__(256) combine_kernel(const float* __restrict__ x,
                                                      float* __restrict__ out) {
    int t = blockIdx.x;
    int tid = threadIdx.x;
    int s0 = g_slot_of[t * TOPK + 0];
    int s1 = g_slot_of[t * TOPK + 1];
    int s2 = g_slot_of[t * TOPK + 2];
    int s3 = g_slot_of[t * TOPK + 3];
    size_t off = (size_t)tid * 4;
    float4 a = *(const float4*)(x + (size_t)t * HDIM + off);
    float4 y0 = *(const float4*)(g_y + (size_t)s0 * HDIM + off);
    float4 y1 = *(const float4*)(g_y + (size_t)s1 * HDIM + off);
    float4 y2 = *(const float4*)(g_y + (size_t)s2 * HDIM + off);
    float4 y3 = *(const float4*)(g_y + (size_t)s3 * HDIM + off);
    a.x += y0.x + y1.x + y2.x + y3.x;
    a.y += y0.y + y1.y + y2.y + y3.y;
    a.z += y0.z + y1.z + y2.z + y3.z;
    a.w += y0.w + y1.w + y2.w + y3.w;
    *(float4*)(out + (size_t)t * HDIM + off) = a;
}

// ---------------- launch ----------------
extern "C" void kernel_launch(void* const* d_in, const int* in_sizes, int n_in,
                              void* d_out, int out_size) {
    const float* x      = (const float*)d_in[0];
    const float* nscale = (const float*)d_in[1];
    const float* wg     = (const float*)d_in[2];
    const float* bg     = (const float*)d_in[3];
    const float* w1     = (const float*)d_in[4];
    const float* b1     = (const float*)d_in[5];
    const float* w2     = (const float*)d_in[6];
    const float* b2     = (const float*)d_in[7];
    float* out = (float*)d_out;

    cudaFuncSetAttribute(ffn_kernel<true>,
                         cudaFuncAttributeMaxDynamicSharedMemorySize, SMEM_BYTES);
    cudaFuncSetAttribute(ffn_kernel<false>,
                         cudaFuncAttributeMaxDynamicSharedMemorySize, SMEM_BYTES);

    zero_cnt_kernel<<<1, 32>>>();
    rms_router_kernel<<<T_TOK, 256>>>(x, nscale, wg, bg);
    ffn_kernel<true><<<dim3((2 * IDIM) / BN, T_TOK / BM, NEXP), 256, SMEM_BYTES>>>(w1, b1);
    ffn_kernel<false><<<dim3(HDIM / BN, T_TOK / BM, NEXP), 256, SMEM_BYTES>>>(w2, b2);
    combine_kernel<<<T_TOK, 256>>>(x, out);
}